// round 1
// baseline (speedup 1.0000x reference)
#include <cuda_runtime.h>
#include <math.h>

#define Nn 16
#define Hh 256
#define Ww 256
#define HW (Hh*Ww)

// ---------------- scratch (device globals; no allocation allowed) ----------------
__device__ float g_h1[(size_t)Nn*64*HW];   // 256 MB
__device__ float g_h2[(size_t)Nn*64*HW];   // 256 MB
__device__ float g_f [(size_t)Nn*81*HW];   // 324 MB
__device__ float g_xy[(size_t)Nn*2*HW];    // 8 MB

// ---------------- conv 3x3, small Cin (1 or 2) -> 64, optional relu ----------------
template<int CIN, bool RELU>
__global__ __launch_bounds__(256) void conv_in_small(
    const float* __restrict__ in, const float* __restrict__ w,
    const float* __restrict__ b, float* __restrict__ out)
{
    __shared__ float s_w[64*CIN*9];
    __shared__ float s_b[64];
    int tid = threadIdx.x;
    for (int i = tid; i < 64*CIN*9; i += 256) s_w[i] = w[i];
    if (tid < 64) s_b[tid] = b[tid];
    __syncthreads();

    int px = blockIdx.x*256 + tid;        // grid exactly N*HW/256
    int n = px >> 16; int rem = px & 65535;
    int y = rem >> 8;  int x = rem & 255;

    float iv[CIN*9];
    #pragma unroll
    for (int c = 0; c < CIN; c++)
        #pragma unroll
        for (int kh = 0; kh < 3; kh++)
            #pragma unroll
            for (int kw = 0; kw < 3; kw++) {
                int yy = y + kh - 1, xx = x + kw - 1;
                float v = 0.f;
                if (yy >= 0 && yy < Hh && xx >= 0 && xx < Ww)
                    v = in[((size_t)n*CIN + c)*HW + yy*Ww + xx];
                iv[c*9 + kh*3 + kw] = v;
            }

    for (int co = 0; co < 64; co++) {
        float a = s_b[co];
        #pragma unroll
        for (int i = 0; i < CIN*9; i++) a += s_w[co*CIN*9 + i] * iv[i];
        if (RELU) a = fmaxf(a, 0.f);
        out[((size_t)n*64 + co)*HW + rem] = a;
    }
}

// ---------------- conv 3x3, Cin=64 -> COUT (64 or 81 padded to 96) ----------------
// Block: one (n, y, 128-px x-strip). Threads = COUT_PAD*4. Each thread: 8 px x 4 co.
// ci chunked by 8 to keep static smem < 48KB.
template<int COUT_PAD, int COUT, bool RELU>
__global__ __launch_bounds__(COUT_PAD*4) void conv64(
    const float* __restrict__ in, const float* __restrict__ w,
    const float* __restrict__ b, float* __restrict__ out)
{
    constexpr int T = COUT_PAD*4;
    __shared__ float s_in[8*3*130];          // 8 ci x 3 rows x 130 cols
    __shared__ float s_w[72*COUT_PAD];       // (ci*9+k) x co

    int bid = blockIdx.x;                    // N*H*2 blocks
    int xseg = bid & 1;
    int y    = (bid >> 1) & 255;
    int n    = bid >> 9;
    int x0   = xseg * 128;

    int tid = threadIdx.x;
    int pg  = tid & 15;                      // pixel lane (consecutive in warp -> no LDS conflicts)
    int cg  = tid >> 4;
    int co_base = cg * 4;

    float acc[8][4];
    #pragma unroll
    for (int p = 0; p < 8; p++)
        #pragma unroll
        for (int j = 0; j < 4; j++) acc[p][j] = 0.f;

    const float* in_n = in + (size_t)n*64*HW;

    for (int cc = 0; cc < 8; cc++) {
        int ci0 = cc * 8;
        // stage input tile: 8 x 3 x 130
        for (int idx = tid; idx < 8*3*130; idx += T) {
            int c  = idx / 390;
            int rm = idx % 390;
            int r  = rm / 130;
            int cx = rm % 130;
            int yy = y + r - 1;
            int xx = x0 + cx - 1;
            float v = 0.f;
            if (yy >= 0 && yy < Hh && xx >= 0 && xx < Ww)
                v = in_n[(size_t)(ci0 + c)*HW + yy*Ww + xx];
            s_in[idx] = v;
        }
        // stage weights: s_w[(ci*9+k)*COUT_PAD + co]
        for (int idx = tid; idx < 72*COUT_PAD; idx += T) {
            int co = idx % COUT_PAD;
            int ck = idx / COUT_PAD;
            int ci = ck / 9, k = ck % 9;
            float v = 0.f;
            if (co < COUT) v = w[((size_t)co*64 + ci0 + ci)*9 + k];
            s_w[idx] = v;
        }
        __syncthreads();

        #pragma unroll 1
        for (int ci = 0; ci < 8; ci++) {
            #pragma unroll
            for (int kh = 0; kh < 3; kh++) {
                const float* row = &s_in[(ci*3 + kh)*130];
                #pragma unroll
                for (int kw = 0; kw < 3; kw++) {
                    float4 wv = *(const float4*)&s_w[(ci*9 + kh*3 + kw)*COUT_PAD + co_base];
                    #pragma unroll
                    for (int p = 0; p < 8; p++) {
                        float iv = row[pg + p*16 + kw];
                        acc[p][0] += iv * wv.x;
                        acc[p][1] += iv * wv.y;
                        acc[p][2] += iv * wv.z;
                        acc[p][3] += iv * wv.w;
                    }
                }
            }
        }
        __syncthreads();
    }

    #pragma unroll
    for (int j = 0; j < 4; j++) {
        int co = co_base + j;
        if (co < COUT) {
            float bias = b[co];
            #pragma unroll
            for (int p = 0; p < 8; p++) {
                float v = acc[p][j] + bias;
                if (RELU) v = fmaxf(v, 0.f);
                out[((size_t)n*COUT + co)*HW + y*Ww + x0 + pg + p*16] = v;
            }
        }
    }
}

// ---------------- softmax over 81 taps + pixel-adaptive 9x9 filtering ----------------
__global__ __launch_bounds__(256) void softmax_filter(
    const float* __restrict__ logits, const float* __restrict__ src,
    float* __restrict__ out, int sel)
{
    int px = blockIdx.x*256 + threadIdx.x;   // N*HW total
    int n = px >> 16; int rem = px & 65535;
    int y = rem >> 8;  int x = rem & 255;

    const float* lp = logits + (size_t)n*81*HW + rem;
    float f[81];
    float mx = -1e30f;
    #pragma unroll
    for (int k = 0; k < 81; k++) { f[k] = lp[(size_t)k*HW]; mx = fmaxf(mx, f[k]); }
    float s = 0.f;
    #pragma unroll
    for (int k = 0; k < 81; k++) { f[k] = __expf(f[k] - mx); s += f[k]; }
    float inv = 1.f / s;

    const float* sp = src + (size_t)n*HW;
    float acc = 0.f;
    #pragma unroll
    for (int kh = 0; kh < 9; kh++) {
        int yy = y + kh - 4;
        if (yy < 0 || yy >= Hh) continue;
        #pragma unroll
        for (int kw = 0; kw < 9; kw++) {
            int xx = x + kw - 4;
            if (xx < 0 || xx >= Ww) continue;
            acc += f[kh*9 + kw] * sp[yy*Ww + xx];
        }
    }
    out[((size_t)n*2 + sel)*HW + rem] = acc * inv;
}

// ---------------- conv 3x3, 64 -> 1 ----------------
__global__ __launch_bounds__(256) void conv_out1(
    const float* __restrict__ in, const float* __restrict__ w,
    const float* __restrict__ b, float* __restrict__ out)
{
    __shared__ float s_w[576];
    int tid = threadIdx.x;
    for (int i = tid; i < 576; i += 256) s_w[i] = w[i];
    __syncthreads();

    int px = blockIdx.x*256 + tid;
    int n = px >> 16; int rem = px & 65535;
    int y = rem >> 8;  int x = rem & 255;

    float a = b[0];
    const float* in_n = in + (size_t)n*64*HW;
    for (int c = 0; c < 64; c++) {
        #pragma unroll
        for (int kh = 0; kh < 3; kh++) {
            int yy = y + kh - 1;
            if (yy < 0 || yy >= Hh) continue;
            #pragma unroll
            for (int kw = 0; kw < 3; kw++) {
                int xx = x + kw - 1;
                if (xx < 0 || xx >= Ww) continue;
                a += s_w[c*9 + kh*3 + kw] * in_n[(size_t)c*HW + yy*Ww + xx];
            }
        }
    }
    out[px] = a;
}

// ---------------- launch ----------------
extern "C" void kernel_launch(void* const* d_in, const int* in_sizes, int n_in,
                              void* d_out, int out_size)
{
    const float* x     = (const float*)d_in[0];
    const float* g     = (const float*)d_in[1];
    const float* fx_w1 = (const float*)d_in[2];
    const float* fx_b1 = (const float*)d_in[3];
    const float* fx_w2 = (const float*)d_in[4];
    const float* fx_b2 = (const float*)d_in[5];
    const float* fx_w3 = (const float*)d_in[6];
    const float* fx_b3 = (const float*)d_in[7];
    const float* fg_w1 = (const float*)d_in[8];
    const float* fg_b1 = (const float*)d_in[9];
    const float* fg_w2 = (const float*)d_in[10];
    const float* fg_b2 = (const float*)d_in[11];
    const float* fg_w3 = (const float*)d_in[12];
    const float* fg_b3 = (const float*)d_in[13];
    const float* c1_w  = (const float*)d_in[14];
    const float* c1_b  = (const float*)d_in[15];
    const float* c2_w  = (const float*)d_in[16];
    const float* c2_b  = (const float*)d_in[17];
    const float* c3_w  = (const float*)d_in[18];
    const float* c3_b  = (const float*)d_in[19];
    float* out = (float*)d_out;

    float *h1, *h2, *f, *xy;
    cudaGetSymbolAddress((void**)&h1, g_h1);
    cudaGetSymbolAddress((void**)&h2, g_h2);
    cudaGetSymbolAddress((void**)&f,  g_f);
    cudaGetSymbolAddress((void**)&xy, g_xy);

    const int PIX_BLOCKS = Nn*HW/256;      // 65536
    const int C64_BLOCKS = Nn*Hh*2;        // 8192

    // x head
    conv_in_small<1, true><<<PIX_BLOCKS, 256>>>(x, fx_w1, fx_b1, h1);
    conv64<64, 64, true><<<C64_BLOCKS, 256>>>(h1, fx_w2, fx_b2, h2);
    conv64<96, 81, false><<<C64_BLOCKS, 384>>>(h2, fx_w3, fx_b3, f);
    softmax_filter<<<PIX_BLOCKS, 256>>>(f, x, xy, 0);

    // g head
    conv_in_small<1, true><<<PIX_BLOCKS, 256>>>(g, fg_w1, fg_b1, h1);
    conv64<64, 64, true><<<C64_BLOCKS, 256>>>(h1, fg_w2, fg_b2, h2);
    conv64<96, 81, false><<<C64_BLOCKS, 384>>>(h2, fg_w3, fg_b3, f);
    softmax_filter<<<PIX_BLOCKS, 256>>>(f, g, xy, 1);

    // fusion head
    conv_in_small<2, true><<<PIX_BLOCKS, 256>>>(xy, c1_w, c1_b, h1);
    conv64<64, 64, true><<<C64_BLOCKS, 256>>>(h1, c2_w, c2_b, h2);
    conv_out1<<<PIX_BLOCKS, 256>>>(h2, c3_w, c3_b, out);
}

// round 2
// speedup vs baseline: 1.0449x; 1.0449x over previous
#include <cuda_runtime.h>
#include <math.h>

#define Nn 16
#define Hh 256
#define Ww 256
#define HW (Hh*Ww)

typedef unsigned long long ull;

__device__ __forceinline__ ull pk2(float lo, float hi) {
    ull r; asm("mov.b64 %0, {%1, %2};" : "=l"(r) : "f"(lo), "f"(hi)); return r;
}
__device__ __forceinline__ void upk2(ull v, float& lo, float& hi) {
    asm("mov.b64 {%0, %1}, %2;" : "=f"(lo), "=f"(hi) : "l"(v));
}
__device__ __forceinline__ void fma2(ull& d, ull a, ull b) {
    asm("fma.rn.f32x2 %0, %1, %2, %0;" : "+l"(d) : "l"(a), "l"(b));
}

// ---------------- scratch (device globals; no allocation allowed) ----------------
__device__ float g_h1[(size_t)Nn*64*HW];   // 256 MB
__device__ float g_h2[(size_t)Nn*64*HW];   // 256 MB
__device__ float g_f [(size_t)Nn*81*HW];   // 324 MB
__device__ float g_xy[(size_t)Nn*2*HW];    // 8 MB

// ---------------- conv 3x3, small Cin (1 or 2) -> 64, optional relu ----------------
template<int CIN, bool RELU>
__global__ __launch_bounds__(256) void conv_in_small(
    const float* __restrict__ in, const float* __restrict__ w,
    const float* __restrict__ b, float* __restrict__ out)
{
    __shared__ float s_w[64*CIN*9];
    __shared__ float s_b[64];
    int tid = threadIdx.x;
    for (int i = tid; i < 64*CIN*9; i += 256) s_w[i] = w[i];
    if (tid < 64) s_b[tid] = b[tid];
    __syncthreads();

    int px = blockIdx.x*256 + tid;
    int n = px >> 16; int rem = px & 65535;
    int y = rem >> 8;  int x = rem & 255;

    float iv[CIN*9];
    #pragma unroll
    for (int c = 0; c < CIN; c++)
        #pragma unroll
        for (int kh = 0; kh < 3; kh++)
            #pragma unroll
            for (int kw = 0; kw < 3; kw++) {
                int yy = y + kh - 1, xx = x + kw - 1;
                float v = 0.f;
                if (yy >= 0 && yy < Hh && xx >= 0 && xx < Ww)
                    v = in[((size_t)n*CIN + c)*HW + yy*Ww + xx];
                iv[c*9 + kh*3 + kw] = v;
            }

    for (int co = 0; co < 64; co++) {
        float a = s_b[co];
        #pragma unroll
        for (int i = 0; i < CIN*9; i++) a += s_w[co*CIN*9 + i] * iv[i];
        if (RELU) a = fmaxf(a, 0.f);
        out[((size_t)n*64 + co)*HW + rem] = a;
    }
}

// ---------------- conv 3x3, Cin=64 -> COUT, packed f32x2 over pixel pairs ----------
// Block: one (n, y, 128-px x-strip). pg = tid&15 selects 8 consecutive pixels,
// cg = tid>>4 selects 8 output channels. Each thread: 4 pixel-pairs x 8 co.
// Threads T = 16 * COUT_PAD/8.
template<int COUT_PAD, int COUT, bool RELU>
__global__ __launch_bounds__(16*COUT_PAD/8) void conv64p(
    const float* __restrict__ in, const float* __restrict__ w,
    const float* __restrict__ b, float* __restrict__ out)
{
    constexpr int T = 16*COUT_PAD/8;
    __shared__ float s_in[8*3*132];          // 8 ci x 3 rows x 132 cols (130 used)
    __shared__ float s_w[72*COUT_PAD];       // (ci*9+k) x co

    int bid = blockIdx.x;                    // N*H*2 blocks
    int xseg = bid & 1;
    int y    = (bid >> 1) & 255;
    int n    = bid >> 9;
    int x0   = xseg * 128;

    int tid = threadIdx.x;
    int pg  = tid & 15;                      // pixel group: 8 consecutive px
    int cg  = tid >> 4;
    int co_base = cg * 8;

    ull acc[4][8];
    #pragma unroll
    for (int c = 0; c < 4; c++)
        #pragma unroll
        for (int j = 0; j < 8; j++) acc[c][j] = 0ULL;

    const float* in_n = in + (size_t)n*64*HW;

    for (int cc = 0; cc < 8; cc++) {
        int ci0 = cc * 8;
        // stage input tile: 8 ci x 3 rows x 132 (cols 0..129 valid)
        for (int idx = tid; idx < 8*3*132; idx += T) {
            int c  = idx / 396;
            int rm = idx % 396;
            int r  = rm / 132;
            int cx = rm % 132;
            int yy = y + r - 1;
            int xx = x0 + cx - 1;
            float v = 0.f;
            if (cx < 130 && yy >= 0 && yy < Hh && xx >= 0 && xx < Ww)
                v = in_n[(size_t)(ci0 + c)*HW + yy*Ww + xx];
            s_in[idx] = v;
        }
        // stage weights: s_w[(ci*9+k)*COUT_PAD + co]
        for (int idx = tid; idx < 72*COUT_PAD; idx += T) {
            int co = idx % COUT_PAD;
            int ck = idx / COUT_PAD;
            int ci = ck / 9, k = ck % 9;
            float v = 0.f;
            if (co < COUT) v = w[((size_t)co*64 + ci0 + ci)*9 + k];
            s_w[idx] = v;
        }
        __syncthreads();

        #pragma unroll 1
        for (int ci = 0; ci < 8; ci++) {
            #pragma unroll
            for (int kh = 0; kh < 3; kh++) {
                const float4* rq = (const float4*)(s_in + (ci*3 + kh)*132 + pg*8);
                float4 q0 = rq[0], q1 = rq[1], q2 = rq[2];
                // natural pairs (v2c, v2c+1)
                ull A0 = pk2(q0.x, q0.y), A1 = pk2(q0.z, q0.w);
                ull A2 = pk2(q1.x, q1.y), A3 = pk2(q1.z, q1.w);
                ull A4 = pk2(q2.x, q2.y);
                // cross pairs (v2c+1, v2c+2) for kw=1
                ull B0 = pk2(q0.y, q0.z), B1 = pk2(q0.w, q1.x);
                ull B2 = pk2(q1.y, q1.z), B3 = pk2(q1.w, q2.x);
                #pragma unroll
                for (int kw = 0; kw < 3; kw++) {
                    const float4* wq = (const float4*)(s_w + (ci*9 + kh*3 + kw)*COUT_PAD + co_base);
                    float4 w0 = wq[0], w1 = wq[1];
                    ull wd[8];
                    wd[0] = pk2(w0.x, w0.x); wd[1] = pk2(w0.y, w0.y);
                    wd[2] = pk2(w0.z, w0.z); wd[3] = pk2(w0.w, w0.w);
                    wd[4] = pk2(w1.x, w1.x); wd[5] = pk2(w1.y, w1.y);
                    wd[6] = pk2(w1.z, w1.z); wd[7] = pk2(w1.w, w1.w);
                    ull P0, P1, P2, P3;
                    if (kw == 0)      { P0 = A0; P1 = A1; P2 = A2; P3 = A3; }
                    else if (kw == 1) { P0 = B0; P1 = B1; P2 = B2; P3 = B3; }
                    else              { P0 = A1; P1 = A2; P2 = A3; P3 = A4; }
                    #pragma unroll
                    for (int j = 0; j < 8; j++) {
                        fma2(acc[0][j], P0, wd[j]);
                        fma2(acc[1][j], P1, wd[j]);
                        fma2(acc[2][j], P2, wd[j]);
                        fma2(acc[3][j], P3, wd[j]);
                    }
                }
            }
        }
        __syncthreads();
    }

    // epilogue: bias + relu + float2 stores (pixel pairs are adjacent)
    #pragma unroll
    for (int j = 0; j < 8; j++) {
        int co = co_base + j;
        if (co < COUT) {
            float bias = b[co];
            float* op = out + ((size_t)n*COUT + co)*HW + y*Ww + x0 + pg*8;
            #pragma unroll
            for (int c = 0; c < 4; c++) {
                float lo, hi; upk2(acc[c][j], lo, hi);
                lo += bias; hi += bias;
                if (RELU) { lo = fmaxf(lo, 0.f); hi = fmaxf(hi, 0.f); }
                ((float2*)op)[c] = make_float2(lo, hi);
            }
        }
    }
}

// ---------------- softmax over 81 taps + pixel-adaptive 9x9 filtering ----------------
__global__ __launch_bounds__(256) void softmax_filter(
    const float* __restrict__ logits, const float* __restrict__ src,
    float* __restrict__ out, int sel)
{
    int px = blockIdx.x*256 + threadIdx.x;
    int n = px >> 16; int rem = px & 65535;
    int y = rem >> 8;  int x = rem & 255;

    const float* lp = logits + (size_t)n*81*HW + rem;
    float f[81];
    float mx = -1e30f;
    #pragma unroll
    for (int k = 0; k < 81; k++) { f[k] = lp[(size_t)k*HW]; mx = fmaxf(mx, f[k]); }
    float s = 0.f;
    #pragma unroll
    for (int k = 0; k < 81; k++) { f[k] = __expf(f[k] - mx); s += f[k]; }
    float inv = 1.f / s;

    const float* sp = src + (size_t)n*HW;
    float acc = 0.f;
    #pragma unroll
    for (int kh = 0; kh < 9; kh++) {
        int yy = y + kh - 4;
        if (yy < 0 || yy >= Hh) continue;
        #pragma unroll
        for (int kw = 0; kw < 9; kw++) {
            int xx = x + kw - 4;
            if (xx < 0 || xx >= Ww) continue;
            acc += f[kh*9 + kw] * sp[yy*Ww + xx];
        }
    }
    out[((size_t)n*2 + sel)*HW + rem] = acc * inv;
}

// ---------------- conv 3x3, 64 -> 1 ----------------
__global__ __launch_bounds__(256) void conv_out1(
    const float* __restrict__ in, const float* __restrict__ w,
    const float* __restrict__ b, float* __restrict__ out)
{
    __shared__ float s_w[576];
    int tid = threadIdx.x;
    for (int i = tid; i < 576; i += 256) s_w[i] = w[i];
    __syncthreads();

    int px = blockIdx.x*256 + tid;
    int n = px >> 16; int rem = px & 65535;
    int y = rem >> 8;  int x = rem & 255;

    float a = b[0];
    const float* in_n = in + (size_t)n*64*HW;
    for (int c = 0; c < 64; c++) {
        #pragma unroll
        for (int kh = 0; kh < 3; kh++) {
            int yy = y + kh - 1;
            if (yy < 0 || yy >= Hh) continue;
            #pragma unroll
            for (int kw = 0; kw < 3; kw++) {
                int xx = x + kw - 1;
                if (xx < 0 || xx >= Ww) continue;
                a += s_w[c*9 + kh*3 + kw] * in_n[(size_t)c*HW + yy*Ww + xx];
            }
        }
    }
    out[px] = a;
}

// ---------------- launch ----------------
extern "C" void kernel_launch(void* const* d_in, const int* in_sizes, int n_in,
                              void* d_out, int out_size)
{
    const float* x     = (const float*)d_in[0];
    const float* g     = (const float*)d_in[1];
    const float* fx_w1 = (const float*)d_in[2];
    const float* fx_b1 = (const float*)d_in[3];
    const float* fx_w2 = (const float*)d_in[4];
    const float* fx_b2 = (const float*)d_in[5];
    const float* fx_w3 = (const float*)d_in[6];
    const float* fx_b3 = (const float*)d_in[7];
    const float* fg_w1 = (const float*)d_in[8];
    const float* fg_b1 = (const float*)d_in[9];
    const float* fg_w2 = (const float*)d_in[10];
    const float* fg_b2 = (const float*)d_in[11];
    const float* fg_w3 = (const float*)d_in[12];
    const float* fg_b3 = (const float*)d_in[13];
    const float* c1_w  = (const float*)d_in[14];
    const float* c1_b  = (const float*)d_in[15];
    const float* c2_w  = (const float*)d_in[16];
    const float* c2_b  = (const float*)d_in[17];
    const float* c3_w  = (const float*)d_in[18];
    const float* c3_b  = (const float*)d_in[19];
    float* out = (float*)d_out;

    float *h1, *h2, *f, *xy;
    cudaGetSymbolAddress((void**)&h1, g_h1);
    cudaGetSymbolAddress((void**)&h2, g_h2);
    cudaGetSymbolAddress((void**)&f,  g_f);
    cudaGetSymbolAddress((void**)&xy, g_xy);

    const int PIX_BLOCKS = Nn*HW/256;      // 65536
    const int C64_BLOCKS = Nn*Hh*2;        // 8192

    // x head
    conv_in_small<1, true><<<PIX_BLOCKS, 256>>>(x, fx_w1, fx_b1, h1);
    conv64p<64, 64, true><<<C64_BLOCKS, 128>>>(h1, fx_w2, fx_b2, h2);
    conv64p<88, 81, false><<<C64_BLOCKS, 176>>>(h2, fx_w3, fx_b3, f);
    softmax_filter<<<PIX_BLOCKS, 256>>>(f, x, xy, 0);

    // g head
    conv_in_small<1, true><<<PIX_BLOCKS, 256>>>(g, fg_w1, fg_b1, h1);
    conv64p<64, 64, true><<<C64_BLOCKS, 128>>>(h1, fg_w2, fg_b2, h2);
    conv64p<88, 81, false><<<C64_BLOCKS, 176>>>(h2, fg_w3, fg_b3, f);
    softmax_filter<<<PIX_BLOCKS, 256>>>(f, g, xy, 1);

    // fusion head
    conv_in_small<2, true><<<PIX_BLOCKS, 256>>>(xy, c1_w, c1_b, h1);
    conv64p<64, 64, true><<<C64_BLOCKS, 128>>>(h1, c2_w, c2_b, h2);
    conv_out1<<<PIX_BLOCKS, 256>>>(h2, c3_w, c3_b, out);
}

// round 4
// speedup vs baseline: 2.7405x; 2.6227x over previous
#include <cuda_runtime.h>
#include <cuda_bf16.h>
#include <cstdint>
#include <math.h>

#define Nn 16
#define Hh 256
#define Ww 256
#define HW (Hh*Ww)

// ---------------- scratch (device globals; no allocation allowed) ----------------
__device__ __nv_bfloat16 g_h1h[(size_t)Nn*HW*64];
__device__ __nv_bfloat16 g_h1l[(size_t)Nn*HW*64];
__device__ __nv_bfloat16 g_h2h[(size_t)Nn*HW*64];
__device__ __nv_bfloat16 g_h2l[(size_t)Nn*HW*64];
__device__ float g_f [(size_t)Nn*HW*88];
__device__ float g_xy[(size_t)Nn*2*HW];
__device__ __nv_bfloat16 g_wp[9*2*88*64];

__device__ __forceinline__ void bsplit(float v, unsigned short& h, unsigned short& l) {
    __nv_bfloat16 hb = __float2bfloat16(v);
    float hf = __bfloat162float(hb);
    __nv_bfloat16 lb = __float2bfloat16(v - hf);
    h = __bfloat16_as_ushort(hb);
    l = __bfloat16_as_ushort(lb);
}

__device__ __forceinline__ void mma_bf16(float* c, uint32_t a0, uint32_t a1, uint32_t a2, uint32_t a3,
                                         uint32_t b0, uint32_t b1) {
    asm volatile("mma.sync.aligned.m16n8k16.row.col.f32.bf16.bf16.f32 "
        "{%0,%1,%2,%3},{%4,%5,%6,%7},{%8,%9},{%0,%1,%2,%3};"
        : "+f"(c[0]), "+f"(c[1]), "+f"(c[2]), "+f"(c[3])
        : "r"(a0), "r"(a1), "r"(a2), "r"(a3), "r"(b0), "r"(b1));
}

// ---------------- weight prepack: w[co][ci][3][3] fp32 -> [tap][half][co_pad][ci] bf16 ----
template<int CP, int CO>
__global__ void prepack_w(const float* __restrict__ w, __nv_bfloat16* __restrict__ o) {
    int idx = blockIdx.x * 256 + threadIdx.x;
    if (idx >= CP * 64) return;
    int co = idx >> 6, ci = idx & 63;
    #pragma unroll
    for (int tap = 0; tap < 9; tap++) {
        float v = (co < CO) ? w[((size_t)co * 64 + ci) * 9 + tap] : 0.f;
        unsigned short h, l; bsplit(v, h, l);
        o[((size_t)(tap*2+0) * CP + co) * 64 + ci] = __ushort_as_bfloat16(h);
        o[((size_t)(tap*2+1) * CP + co) * 64 + ci] = __ushort_as_bfloat16(l);
    }
}

// ---------------- conv 3x3, small Cin (1 or 2) -> 64 relu, writes split-bf16 NHWC ----------
template<int CIN>
__global__ __launch_bounds__(256) void conv_in_small(
    const float* __restrict__ in, const float* __restrict__ w,
    const float* __restrict__ b, __nv_bfloat16* __restrict__ ohi, __nv_bfloat16* __restrict__ olo)
{
    __shared__ float s_w[64*CIN*9];
    __shared__ float s_b[64];
    int tid = threadIdx.x;
    for (int i = tid; i < 64*CIN*9; i += 256) s_w[i] = w[i];
    if (tid < 64) s_b[tid] = b[tid];
    __syncthreads();

    int px = blockIdx.x*256 + tid;
    int n = px >> 16; int rem = px & 65535;
    int y = rem >> 8;  int x = rem & 255;

    float iv[CIN*9];
    #pragma unroll
    for (int c = 0; c < CIN; c++)
        #pragma unroll
        for (int kh = 0; kh < 3; kh++)
            #pragma unroll
            for (int kw = 0; kw < 3; kw++) {
                int yy = y + kh - 1, xx = x + kw - 1;
                float v = 0.f;
                if (yy >= 0 && yy < Hh && xx >= 0 && xx < Ww)
                    v = in[((size_t)n*CIN + c)*HW + yy*Ww + xx];
                iv[c*9 + kh*3 + kw] = v;
            }

    float a[64];
    #pragma unroll
    for (int co = 0; co < 64; co++) {
        float s = s_b[co];
        #pragma unroll
        for (int i = 0; i < CIN*9; i++) s += s_w[co*CIN*9 + i] * iv[i];
        a[co] = fmaxf(s, 0.f);
    }

    char* ph = (char*)ohi + (size_t)px * 128;
    char* pl = (char*)olo + (size_t)px * 128;
    #pragma unroll
    for (int q = 0; q < 8; q++) {
        uint32_t hw[4], lw[4];
        #pragma unroll
        for (int t = 0; t < 4; t++) {
            int co = q*8 + t*2;
            unsigned short h0, l0, h1, l1;
            bsplit(a[co], h0, l0); bsplit(a[co+1], h1, l1);
            hw[t] = (uint32_t)h0 | ((uint32_t)h1 << 16);
            lw[t] = (uint32_t)l0 | ((uint32_t)l1 << 16);
        }
        *(uint4*)(ph + q*16) = make_uint4(hw[0], hw[1], hw[2], hw[3]);
        *(uint4*)(pl + q*16) = make_uint4(lw[0], lw[1], lw[2], lw[3]);
    }
}

// ---------------- mma.sync conv 3x3, 64 -> CO, split-bf16 3-pass ----------------
// CTA: 128 thr = 4 warps. M = 128 px (2 y-rows x 64 x). Warp: 32 px x full N.
template<int NT, int CO, bool RELU, bool SPLIT>
__global__ __launch_bounds__(128) void conv64m(
    const __nv_bfloat16* __restrict__ ihi, const __nv_bfloat16* __restrict__ ilo,
    const __nv_bfloat16* __restrict__ wp, const float* __restrict__ bias,
    __nv_bfloat16* __restrict__ ohi, __nv_bfloat16* __restrict__ olo,
    float* __restrict__ of)
{
    constexpr int CP = NT * 8;
    constexpr int AH = 4*68*144;          // bytes per A half
    constexpr int WH = CP*144;            // bytes per W half
    extern __shared__ char sm[];
    char* sAh = sm;
    char* sAl = sm + AH;
    char* sWh = sm + 2*AH;
    char* sWl = sm + 2*AH + WH;
    float* s_bias = (float*)(sm + 2*AH + 2*WH);

    int tid = threadIdx.x;
    int lane = tid & 31, wid = tid >> 5;
    int lg = lane >> 2, lt = lane & 3;
    int py = wid >> 1, xb = (wid & 1) * 32;

    int bid = blockIdx.x;                 // 16n x 128yp x 4xq
    int xq = bid & 3;
    int yp = (bid >> 2) & 127;
    int n  = bid >> 9;
    int y0 = yp * 2, x0 = xq * 64;
    size_t nbase = (size_t)n * 65536;

    // stage A (once) -------------------------------------------------------
    for (int idx = tid; idx < 4*66*8; idx += 128) {
        int c = idx & 7, e = idx >> 3;
        int row = e / 66, px = e - row*66;
        int gy = y0 + row - 1, gx = x0 + px - 1;
        uint4 vh = make_uint4(0,0,0,0), vl = vh;
        if ((unsigned)gy < 256u && (unsigned)gx < 256u) {
            size_t pix = nbase + gy*256 + gx;
            vh = *(const uint4*)((const char*)ihi + pix*128 + c*16);
            vl = *(const uint4*)((const char*)ilo + pix*128 + c*16);
        }
        int so = (row*68 + px)*144 + c*16;
        *(uint4*)(sAh + so) = vh;
        *(uint4*)(sAl + so) = vl;
    }
    if (tid < CP) s_bias[tid] = (tid < CO) ? bias[tid] : 0.f;

    float acc[2][NT][4];
    #pragma unroll
    for (int mt = 0; mt < 2; mt++)
        #pragma unroll
        for (int nt = 0; nt < NT; nt++)
            #pragma unroll
            for (int j = 0; j < 4; j++) acc[mt][nt][j] = 0.f;

    int bbase = lg*144 + lt*4;

    for (int kh = 0; kh < 3; kh++)
    for (int kw = 0; kw < 3; kw++) {
        int tap = kh*3 + kw;
        // stage W(tap)
        for (int idx = tid; idx < CP*8; idx += 128) {
            int c = idx & 7, co = idx >> 3;
            const char* srcH = (const char*)wp + ((size_t)(tap*2+0)*CP + co)*128 + c*16;
            const char* srcL = (const char*)wp + ((size_t)(tap*2+1)*CP + co)*128 + c*16;
            *(uint4*)(sWh + co*144 + c*16) = *(const uint4*)srcH;
            *(uint4*)(sWl + co*144 + c*16) = *(const uint4*)srcL;
        }
        __syncthreads();

        int abase = ((py + kh)*68 + xb + lg + kw)*144 + lt*4;
        #pragma unroll
        for (int k = 0; k < 4; k++) {
            uint32_t ah[2][4], al[2][4];
            #pragma unroll
            for (int mt = 0; mt < 2; mt++) {
                int b0 = abase + mt*2304 + k*32;
                ah[mt][0] = *(const uint32_t*)(sAh + b0);
                ah[mt][1] = *(const uint32_t*)(sAh + b0 + 1152);
                ah[mt][2] = *(const uint32_t*)(sAh + b0 + 16);
                ah[mt][3] = *(const uint32_t*)(sAh + b0 + 1168);
                al[mt][0] = *(const uint32_t*)(sAl + b0);
                al[mt][1] = *(const uint32_t*)(sAl + b0 + 1152);
                al[mt][2] = *(const uint32_t*)(sAl + b0 + 16);
                al[mt][3] = *(const uint32_t*)(sAl + b0 + 1168);
            }
            #pragma unroll
            for (int nt = 0; nt < NT; nt++) {
                int bo = bbase + nt*1152 + k*32;
                uint32_t bh0 = *(const uint32_t*)(sWh + bo);
                uint32_t bh1 = *(const uint32_t*)(sWh + bo + 16);
                uint32_t bl0 = *(const uint32_t*)(sWl + bo);
                uint32_t bl1 = *(const uint32_t*)(sWl + bo + 16);
                #pragma unroll
                for (int mt = 0; mt < 2; mt++) {
                    mma_bf16(acc[mt][nt], ah[mt][0], ah[mt][1], ah[mt][2], ah[mt][3], bh0, bh1);
                    mma_bf16(acc[mt][nt], al[mt][0], al[mt][1], al[mt][2], al[mt][3], bh0, bh1);
                    mma_bf16(acc[mt][nt], ah[mt][0], ah[mt][1], ah[mt][2], ah[mt][3], bl0, bl1);
                }
            }
        }
        __syncthreads();
    }

    // epilogue -------------------------------------------------------------
    #pragma unroll
    for (int mt = 0; mt < 2; mt++) {
        size_t pix0 = nbase + (size_t)(y0 + py)*256 + x0 + xb + mt*16 + lg;
        #pragma unroll
        for (int nt = 0; nt < NT; nt++) {
            int co = nt*8 + lt*2;
            float b0 = s_bias[co], b1 = s_bias[co+1];
            float v00 = acc[mt][nt][0] + b0, v01 = acc[mt][nt][1] + b1;
            float v10 = acc[mt][nt][2] + b0, v11 = acc[mt][nt][3] + b1;
            if (RELU) {
                v00 = fmaxf(v00, 0.f); v01 = fmaxf(v01, 0.f);
                v10 = fmaxf(v10, 0.f); v11 = fmaxf(v11, 0.f);
            }
            if (SPLIT) {
                unsigned short h0,l0,h1,l1;
                bsplit(v00,h0,l0); bsplit(v01,h1,l1);
                *(uint32_t*)((char*)ohi + pix0*128 + co*2) = (uint32_t)h0 | ((uint32_t)h1<<16);
                *(uint32_t*)((char*)olo + pix0*128 + co*2) = (uint32_t)l0 | ((uint32_t)l1<<16);
                bsplit(v10,h0,l0); bsplit(v11,h1,l1);
                *(uint32_t*)((char*)ohi + (pix0+8)*128 + co*2) = (uint32_t)h0 | ((uint32_t)h1<<16);
                *(uint32_t*)((char*)olo + (pix0+8)*128 + co*2) = (uint32_t)l0 | ((uint32_t)l1<<16);
            } else {
                *(float2*)(of + pix0*88 + co) = make_float2(v00, v01);
                *(float2*)(of + (pix0+8)*88 + co) = make_float2(v10, v11);
            }
        }
    }
}

// ---------------- softmax over 81 taps + pixel-adaptive 9x9 filtering ----------------
__global__ __launch_bounds__(256) void softmax_filter(
    const float* __restrict__ logits, const float* __restrict__ src,
    float* __restrict__ out, int sel)
{
    int px = blockIdx.x*256 + threadIdx.x;
    int n = px >> 16; int rem = px & 65535;
    int y = rem >> 8;  int x = rem & 255;

    const float* lp = logits + (size_t)px * 88;
    float f[81];
    float mx = -1e30f;
    #pragma unroll
    for (int k = 0; k < 81; k++) { f[k] = lp[k]; mx = fmaxf(mx, f[k]); }
    float s = 0.f;
    #pragma unroll
    for (int k = 0; k < 81; k++) { f[k] = __expf(f[k] - mx); s += f[k]; }
    float inv = 1.f / s;

    const float* sp = src + (size_t)n*HW;
    float acc = 0.f;
    #pragma unroll
    for (int kh = 0; kh < 9; kh++) {
        int yy = y + kh - 4;
        if (yy < 0 || yy >= Hh) continue;
        #pragma unroll
        for (int kw = 0; kw < 9; kw++) {
            int xx = x + kw - 4;
            if (xx < 0 || xx >= Ww) continue;
            acc += f[kh*9 + kw] * sp[yy*Ww + xx];
        }
    }
    out[((size_t)n*2 + sel)*HW + rem] = acc * inv;
}

// ---------------- conv 3x3, 64 -> 1, reads split-bf16 NHWC ----------------
__global__ __launch_bounds__(64) void conv_out1(
    const __nv_bfloat16* __restrict__ ihi, const __nv_bfloat16* __restrict__ ilo,
    const float* __restrict__ w, const float* __restrict__ b, float* __restrict__ out)
{
    extern __shared__ char sm[];
    char* sh = sm;                        // 3*66*144
    char* sl = sm + 3*66*144;
    float* sw = (float*)(sm + 2*3*66*144);

    int tid = threadIdx.x;
    int bid = blockIdx.x;                 // 16n x 256y x 4xq
    int xq = bid & 3;
    int y  = (bid >> 2) & 255;
    int n  = bid >> 10;
    int x0 = xq * 64;
    size_t nbase = (size_t)n * 65536;

    for (int idx = tid; idx < 576; idx += 64) sw[idx] = w[idx];
    for (int idx = tid; idx < 3*66*8; idx += 64) {
        int c = idx & 7, e = idx >> 3;
        int row = e / 66, px = e - row*66;
        int gy = y + row - 1, gx = x0 + px - 1;
        uint4 vh = make_uint4(0,0,0,0), vl = vh;
        if ((unsigned)gy < 256u && (unsigned)gx < 256u) {
            size_t pix = nbase + gy*256 + gx;
            vh = *(const uint4*)((const char*)ihi + pix*128 + c*16);
            vl = *(const uint4*)((const char*)ilo + pix*128 + c*16);
        }
        int so = (row*66 + px)*144 + c*16;
        *(uint4*)(sh + so) = vh;
        *(uint4*)(sl + so) = vl;
    }
    __syncthreads();

    float a = b[0];
    #pragma unroll
    for (int kh = 0; kh < 3; kh++)
    #pragma unroll
    for (int kw = 0; kw < 3; kw++) {
        int base = (kh*66 + tid + kw)*144;
        int tap = kh*3 + kw;
        #pragma unroll
        for (int cq = 0; cq < 8; cq++) {
            uint4 H = *(const uint4*)(sh + base + cq*16);
            uint4 L = *(const uint4*)(sl + base + cq*16);
            uint32_t hw[4] = {H.x, H.y, H.z, H.w};
            uint32_t lw[4] = {L.x, L.y, L.z, L.w};
            #pragma unroll
            for (int t = 0; t < 4; t++) {
                float v0 = __uint_as_float(hw[t] << 16) + __uint_as_float(lw[t] << 16);
                float v1 = __uint_as_float(hw[t] & 0xFFFF0000u) + __uint_as_float(lw[t] & 0xFFFF0000u);
                int ci = cq*8 + t*2;
                a += sw[ci*9 + tap] * v0;
                a += sw[(ci+1)*9 + tap] * v1;
            }
        }
    }
    out[nbase + (size_t)y*256 + x0 + tid] = a;
}

// ---------------- launch ----------------
extern "C" void kernel_launch(void* const* d_in, const int* in_sizes, int n_in,
                              void* d_out, int out_size)
{
    const float* x     = (const float*)d_in[0];
    const float* g     = (const float*)d_in[1];
    const float* fx_w1 = (const float*)d_in[2];
    const float* fx_b1 = (const float*)d_in[3];
    const float* fx_w2 = (const float*)d_in[4];
    const float* fx_b2 = (const float*)d_in[5];
    const float* fx_w3 = (const float*)d_in[6];
    const float* fx_b3 = (const float*)d_in[7];
    const float* fg_w1 = (const float*)d_in[8];
    const float* fg_b1 = (const float*)d_in[9];
    const float* fg_w2 = (const float*)d_in[10];
    const float* fg_b2 = (const float*)d_in[11];
    const float* fg_w3 = (const float*)d_in[12];
    const float* fg_b3 = (const float*)d_in[13];
    const float* c1_w  = (const float*)d_in[14];
    const float* c1_b  = (const float*)d_in[15];
    const float* c2_w  = (const float*)d_in[16];
    const float* c2_b  = (const float*)d_in[17];
    const float* c3_w  = (const float*)d_in[18];
    const float* c3_b  = (const float*)d_in[19];
    float* out = (float*)d_out;

    __nv_bfloat16 *h1h, *h1l, *h2h, *h2l, *wp;
    float *f, *xy;
    cudaGetSymbolAddress((void**)&h1h, g_h1h);
    cudaGetSymbolAddress((void**)&h1l, g_h1l);
    cudaGetSymbolAddress((void**)&h2h, g_h2h);
    cudaGetSymbolAddress((void**)&h2l, g_h2l);
    cudaGetSymbolAddress((void**)&f,  g_f);
    cudaGetSymbolAddress((void**)&xy, g_xy);
    cudaGetSymbolAddress((void**)&wp, g_wp);

    const int PIX_BLOCKS = Nn*HW/256;      // 65536
    const int C64_BLOCKS = Nn*128*4;       // 8192
    const int OUT_BLOCKS = Nn*256*4;       // 16384

    const int SM64 = 2*(4*68*144) + 2*(64*144) + 64*4;   // 97024
    const int SM88 = 2*(4*68*144) + 2*(88*144) + 88*4;   // 104032
    const int SMO  = 2*(3*66*144) + 576*4;               // 59328

    cudaFuncSetAttribute((const void*)conv64m<8, 64, true, true>,
                         cudaFuncAttributeMaxDynamicSharedMemorySize, SM64);
    cudaFuncSetAttribute((const void*)conv64m<11, 81, false, false>,
                         cudaFuncAttributeMaxDynamicSharedMemorySize, SM88);
    cudaFuncSetAttribute((const void*)conv_out1,
                         cudaFuncAttributeMaxDynamicSharedMemorySize, SMO);

    // x head
    conv_in_small<1><<<PIX_BLOCKS, 256>>>(x, fx_w1, fx_b1, h1h, h1l);
    prepack_w<64, 64><<<16, 256>>>(fx_w2, wp);
    conv64m<8, 64, true, true><<<C64_BLOCKS, 128, SM64>>>(h1h, h1l, wp, fx_b2, h2h, h2l, nullptr);
    prepack_w<88, 81><<<22, 256>>>(fx_w3, wp);
    conv64m<11, 81, false, false><<<C64_BLOCKS, 128, SM88>>>(h2h, h2l, wp, fx_b3, nullptr, nullptr, f);
    softmax_filter<<<PIX_BLOCKS, 256>>>(f, x, xy, 0);

    // g head
    conv_in_small<1><<<PIX_BLOCKS, 256>>>(g, fg_w1, fg_b1, h1h, h1l);
    prepack_w<64, 64><<<16, 256>>>(fg_w2, wp);
    conv64m<8, 64, true, true><<<C64_BLOCKS, 128, SM64>>>(h1h, h1l, wp, fg_b2, h2h, h2l, nullptr);
    prepack_w<88, 81><<<22, 256>>>(fg_w3, wp);
    conv64m<11, 81, false, false><<<C64_BLOCKS, 128, SM88>>>(h2h, h2l, wp, fg_b3, nullptr, nullptr, f);
    softmax_filter<<<PIX_BLOCKS, 256>>>(f, g, xy, 1);

    // fusion head
    conv_in_small<2><<<PIX_BLOCKS, 256>>>(xy, c1_w, c1_b, h1h, h1l);
    prepack_w<64, 64><<<16, 256>>>(c2_w, wp);
    conv64m<8, 64, true, true><<<C64_BLOCKS, 128, SM64>>>(h1h, h1l, wp, c2_b, h2h, h2l, nullptr);
    conv_out1<<<OUT_BLOCKS, 64, SMO>>>(h2h, h2l, c3_w, c3_b, out);
}

// round 5
// speedup vs baseline: 4.3981x; 1.6049x over previous
#include <cuda_runtime.h>
#include <cuda_fp16.h>
#include <cstdint>
#include <math.h>

#define Nn 16
#define Hh 256
#define Ww 256
#define HW (Hh*Ww)

// ---------------- scratch (device globals; no allocation allowed) ----------------
__device__ __half g_h1h[(size_t)Nn*HW*64];
__device__ __half g_h1l[(size_t)Nn*HW*64];
__device__ __half g_h2h[(size_t)Nn*HW*64];
__device__ __half g_h2l[(size_t)Nn*HW*64];
__device__ float g_xy[(size_t)Nn*2*HW];
__device__ uint32_t g_wq[9*4*11*32*2];   // prepacked B fragments for current conv

__device__ __forceinline__ void hsplit(float v, unsigned short& h, unsigned short& l) {
    __half hb = __float2half_rn(v);
    float hf = __half2float(hb);
    __half lb = __float2half_rn(v - hf);
    h = __half_as_ushort(hb);
    l = __half_as_ushort(lb);
}
__device__ __forceinline__ float h2f(uint32_t u, int hi) {
    return __half2float(__ushort_as_half((unsigned short)(hi ? (u >> 16) : (u & 0xFFFF))));
}

__device__ __forceinline__ void mma_f16(float* c, uint32_t a0, uint32_t a1, uint32_t a2, uint32_t a3,
                                        uint32_t b0, uint32_t b1) {
    asm volatile("mma.sync.aligned.m16n8k16.row.col.f32.f16.f16.f32 "
        "{%0,%1,%2,%3},{%4,%5,%6,%7},{%8,%9},{%0,%1,%2,%3};"
        : "+f"(c[0]), "+f"(c[1]), "+f"(c[2]), "+f"(c[3])
        : "r"(a0), "r"(a1), "r"(a2), "r"(a3), "r"(b0), "r"(b1));
}

// ------------- weight prepack: w[co][ci][3][3] fp32 -> B fragments [tap][k][nt][lane][2]u32 ----
template<int NT, int CO>
__global__ void prepack_wq(const float* __restrict__ w, uint32_t* __restrict__ o) {
    int idx = blockIdx.x * 256 + threadIdx.x;
    if (idx >= 9*4*NT*32) return;
    int lane = idx & 31;
    int nt = (idx >> 5) % NT;
    int k  = (idx / (32*NT)) & 3;
    int tap = idx / (32*NT*4);
    int lg = lane >> 2, lt = lane & 3;
    int co = nt*8 + lg;
    auto wv = [&](int ci) -> uint32_t {
        float v = (co < CO) ? w[((size_t)co*64 + ci)*9 + tap] : 0.f;
        return (uint32_t)__half_as_ushort(__float2half_rn(v));
    };
    int c0 = k*16 + lt*2;
    o[idx*2]   = wv(c0)   | (wv(c0+1) << 16);
    o[idx*2+1] = wv(c0+8) | (wv(c0+9) << 16);
}

// ---------------- conv 3x3, small Cin (1 or 2) -> 64 relu, writes split-fp16 NHWC ----------
template<int CIN>
__global__ __launch_bounds__(256) void conv_in_small(
    const float* __restrict__ in, const float* __restrict__ w,
    const float* __restrict__ b, __half* __restrict__ ohi, __half* __restrict__ olo)
{
    __shared__ float s_w[64*CIN*9];
    __shared__ float s_b[64];
    int tid = threadIdx.x;
    for (int i = tid; i < 64*CIN*9; i += 256) s_w[i] = w[i];
    if (tid < 64) s_b[tid] = b[tid];
    __syncthreads();

    int px = blockIdx.x*256 + tid;
    int n = px >> 16; int rem = px & 65535;
    int y = rem >> 8;  int x = rem & 255;

    float iv[CIN*9];
    #pragma unroll
    for (int c = 0; c < CIN; c++)
        #pragma unroll
        for (int kh = 0; kh < 3; kh++)
            #pragma unroll
            for (int kw = 0; kw < 3; kw++) {
                int yy = y + kh - 1, xx = x + kw - 1;
                float v = 0.f;
                if (yy >= 0 && yy < Hh && xx >= 0 && xx < Ww)
                    v = in[((size_t)n*CIN + c)*HW + yy*Ww + xx];
                iv[c*9 + kh*3 + kw] = v;
            }

    float a[64];
    #pragma unroll
    for (int co = 0; co < 64; co++) {
        float s = s_b[co];
        #pragma unroll
        for (int i = 0; i < CIN*9; i++) s += s_w[co*CIN*9 + i] * iv[i];
        a[co] = fmaxf(s, 0.f);
    }

    char* ph = (char*)ohi + (size_t)px * 128;
    char* pl = (char*)olo + (size_t)px * 128;
    #pragma unroll
    for (int q = 0; q < 8; q++) {
        uint32_t hw[4], lw[4];
        #pragma unroll
        for (int t = 0; t < 4; t++) {
            int co = q*8 + t*2;
            unsigned short h0, l0, h1, l1;
            hsplit(a[co], h0, l0); hsplit(a[co+1], h1, l1);
            hw[t] = (uint32_t)h0 | ((uint32_t)h1 << 16);
            lw[t] = (uint32_t)l0 | ((uint32_t)l1 << 16);
        }
        *(uint4*)(ph + q*16) = make_uint4(hw[0], hw[1], hw[2], hw[3]);
        *(uint4*)(pl + q*16) = make_uint4(lw[0], lw[1], lw[2], lw[3]);
    }
}

// ---------------- mma.sync conv 3x3, 64 -> CO, split-fp16 activations, 2-pass -----------
// CTA: 128 thr = 4 warps, M = 128 px (2 y-rows x 64 x). One sync; W direct from L1.
// FUSE: fused bias+softmax(81)+9x9 pixel-adaptive filtering epilogue.
template<int NT, int CO, bool RELU, bool FUSE>
__global__ __launch_bounds__(128) void conv64m(
    const __half* __restrict__ ihi, const __half* __restrict__ ilo,
    const uint32_t* __restrict__ wq, const float* __restrict__ bias,
    __half* __restrict__ ohi, __half* __restrict__ olo,
    const float* __restrict__ src, float* __restrict__ xy, int sel)
{
    constexpr int CP = NT * 8;
    extern __shared__ char sm[];
    char* sAh = sm;                      // 4 rows x 68 px x 144 B
    char* sAl = sm + 39168;
    float* s_bias = (float*)(sm + 78336);

    int tid = threadIdx.x;
    int lane = tid & 31, wid = tid >> 5;
    int lg = lane >> 2, lt = lane & 3;
    int py = wid >> 1, xb = (wid & 1) * 32;

    int bid = blockIdx.x;                // 16n x 128yp x 4xq
    int xq = bid & 3;
    int yp = (bid >> 2) & 127;
    int n  = bid >> 9;
    int y0 = yp * 2, x0 = xq * 64;
    size_t nbase = (size_t)n * 65536;

    // stage A (once) + bias
    for (int idx = tid; idx < 4*66*8; idx += 128) {
        int c = idx & 7, e = idx >> 3;
        int row = e / 66, px = e - row*66;
        int gy = y0 + row - 1, gx = x0 + px - 1;
        uint4 vh = make_uint4(0,0,0,0), vl = vh;
        if ((unsigned)gy < 256u && (unsigned)gx < 256u) {
            size_t pix = nbase + gy*256 + gx;
            vh = *(const uint4*)((const char*)ihi + pix*128 + c*16);
            vl = *(const uint4*)((const char*)ilo + pix*128 + c*16);
        }
        int so = (row*68 + px)*144 + c*16;
        *(uint4*)(sAh + so) = vh;
        *(uint4*)(sAl + so) = vl;
    }
    if (tid < CP) s_bias[tid] = (tid < CO) ? bias[tid] : 0.f;
    __syncthreads();

    float acc[2][NT][4];
    #pragma unroll
    for (int mt = 0; mt < 2; mt++)
        #pragma unroll
        for (int nt = 0; nt < NT; nt++)
            #pragma unroll
            for (int j = 0; j < 4; j++) acc[mt][nt][j] = 0.f;

    #pragma unroll 1
    for (int tap = 0; tap < 9; tap++) {
        int kh = tap / 3, kw = tap - kh*3;
        int abase = ((py + kh)*68 + xb + lg + kw)*144 + lt*4;
        const uint32_t* wt = wq + (size_t)tap*4*NT*64 + lane*2;
        #pragma unroll
        for (int k = 0; k < 4; k++) {
            uint32_t ah[2][4], al[2][4];
            #pragma unroll
            for (int mt = 0; mt < 2; mt++) {
                int b0 = abase + mt*2304 + k*32;
                ah[mt][0] = *(const uint32_t*)(sAh + b0);
                ah[mt][1] = *(const uint32_t*)(sAh + b0 + 1152);
                ah[mt][2] = *(const uint32_t*)(sAh + b0 + 16);
                ah[mt][3] = *(const uint32_t*)(sAh + b0 + 1168);
                al[mt][0] = *(const uint32_t*)(sAl + b0);
                al[mt][1] = *(const uint32_t*)(sAl + b0 + 1152);
                al[mt][2] = *(const uint32_t*)(sAl + b0 + 16);
                al[mt][3] = *(const uint32_t*)(sAl + b0 + 1168);
            }
            const uint32_t* wk = wt + (size_t)k*NT*64;
            #pragma unroll
            for (int nt = 0; nt < NT; nt++) {
                uint2 bb = *(const uint2*)(wk + (size_t)nt*64);
                #pragma unroll
                for (int mt = 0; mt < 2; mt++) {
                    mma_f16(acc[mt][nt], ah[mt][0], ah[mt][1], ah[mt][2], ah[mt][3], bb.x, bb.y);
                    mma_f16(acc[mt][nt], al[mt][0], al[mt][1], al[mt][2], al[mt][3], bb.x, bb.y);
                }
            }
        }
    }

    if (!FUSE) {
        // split-fp16 epilogue
        #pragma unroll
        for (int mt = 0; mt < 2; mt++) {
            size_t pix0 = nbase + (size_t)(y0 + py)*256 + x0 + xb + mt*16 + lg;
            #pragma unroll
            for (int nt = 0; nt < NT; nt++) {
                int co = nt*8 + lt*2;
                float b0 = s_bias[co], b1 = s_bias[co+1];
                float v00 = acc[mt][nt][0] + b0, v01 = acc[mt][nt][1] + b1;
                float v10 = acc[mt][nt][2] + b0, v11 = acc[mt][nt][3] + b1;
                if (RELU) {
                    v00 = fmaxf(v00, 0.f); v01 = fmaxf(v01, 0.f);
                    v10 = fmaxf(v10, 0.f); v11 = fmaxf(v11, 0.f);
                }
                unsigned short h0,l0,h1,l1;
                hsplit(v00,h0,l0); hsplit(v01,h1,l1);
                *(uint32_t*)((char*)ohi + pix0*128 + co*2) = (uint32_t)h0 | ((uint32_t)h1<<16);
                *(uint32_t*)((char*)olo + pix0*128 + co*2) = (uint32_t)l0 | ((uint32_t)l1<<16);
                hsplit(v10,h0,l0); hsplit(v11,h1,l1);
                *(uint32_t*)((char*)ohi + (pix0+8)*128 + co*2) = (uint32_t)h0 | ((uint32_t)h1<<16);
                *(uint32_t*)((char*)olo + (pix0+8)*128 + co*2) = (uint32_t)l0 | ((uint32_t)l1<<16);
            }
        }
    } else {
        // fused softmax over 81 logits + 9x9 pixel-adaptive filtering.
        // Quad (lt=0..3) holds all channels of the same pixels.
        const float* sp = src + nbase;
        int Y = y0 + py;
        #pragma unroll
        for (int mt = 0; mt < 2; mt++) {
            #pragma unroll
            for (int r = 0; r < 2; r++) {
                int X = x0 + xb + mt*16 + lg + r*8;
                float v[NT][2];
                float mx = -1e30f;
                #pragma unroll
                for (int nt = 0; nt < NT; nt++) {
                    #pragma unroll
                    for (int j = 0; j < 2; j++) {
                        int co = nt*8 + lt*2 + j;
                        v[nt][j] = acc[mt][nt][r*2 + j] + s_bias[co];
                        if (co < 81) mx = fmaxf(mx, v[nt][j]);
                    }
                }
                mx = fmaxf(mx, __shfl_xor_sync(0xffffffffu, mx, 1));
                mx = fmaxf(mx, __shfl_xor_sync(0xffffffffu, mx, 2));
                float se = 0.f, fo = 0.f;
                #pragma unroll
                for (int nt = 0; nt < NT; nt++) {
                    #pragma unroll
                    for (int j = 0; j < 2; j++) {
                        int co = nt*8 + lt*2 + j;
                        if (co < 81) {
                            float e = __expf(v[nt][j] - mx);
                            se += e;
                            int kh = co / 9, kw = co - kh*9;
                            int sy = Y + kh - 4, sx = X + kw - 4;
                            float sv = 0.f;
                            if ((unsigned)sy < 256u && (unsigned)sx < 256u)
                                sv = sp[sy*256 + sx];
                            fo += e * sv;
                        }
                    }
                }
                se += __shfl_xor_sync(0xffffffffu, se, 1);
                se += __shfl_xor_sync(0xffffffffu, se, 2);
                fo += __shfl_xor_sync(0xffffffffu, fo, 1);
                fo += __shfl_xor_sync(0xffffffffu, fo, 2);
                if (lt == 0)
                    xy[((size_t)n*2 + sel)*HW + Y*256 + X] = fo / se;
            }
        }
    }
}

// ---------------- conv 3x3, 64 -> 1, reads split-fp16 NHWC ----------------
__global__ __launch_bounds__(64) void conv_out1(
    const __half* __restrict__ ihi, const __half* __restrict__ ilo,
    const float* __restrict__ w, const float* __restrict__ b, float* __restrict__ out)
{
    extern __shared__ char sm[];
    char* sh = sm;                        // 3*66*144
    char* sl = sm + 3*66*144;
    float* sw = (float*)(sm + 2*3*66*144);

    int tid = threadIdx.x;
    int bid = blockIdx.x;                 // 16n x 256y x 4xq
    int xq = bid & 3;
    int y  = (bid >> 2) & 255;
    int n  = bid >> 10;
    int x0 = xq * 64;
    size_t nbase = (size_t)n * 65536;

    for (int idx = tid; idx < 576; idx += 64) sw[idx] = w[idx];
    for (int idx = tid; idx < 3*66*8; idx += 64) {
        int c = idx & 7, e = idx >> 3;
        int row = e / 66, px = e - row*66;
        int gy = y + row - 1, gx = x0 + px - 1;
        uint4 vh = make_uint4(0,0,0,0), vl = vh;
        if ((unsigned)gy < 256u && (unsigned)gx < 256u) {
            size_t pix = nbase + gy*256 + gx;
            vh = *(const uint4*)((const char*)ihi + pix*128 + c*16);
            vl = *(const uint4*)((const char*)ilo + pix*128 + c*16);
        }
        int so = (row*66 + px)*144 + c*16;
        *(uint4*)(sh + so) = vh;
        *(uint4*)(sl + so) = vl;
    }
    __syncthreads();

    float a = b[0];
    #pragma unroll
    for (int kh = 0; kh < 3; kh++)
    #pragma unroll
    for (int kw = 0; kw < 3; kw++) {
        int base = (kh*66 + tid + kw)*144;
        int tap = kh*3 + kw;
        #pragma unroll
        for (int cq = 0; cq < 8; cq++) {
            uint4 H = *(const uint4*)(sh + base + cq*16);
            uint4 L = *(const uint4*)(sl + base + cq*16);
            uint32_t hw[4] = {H.x, H.y, H.z, H.w};
            uint32_t lw[4] = {L.x, L.y, L.z, L.w};
            #pragma unroll
            for (int t = 0; t < 4; t++) {
                float v0 = h2f(hw[t], 0) + h2f(lw[t], 0);
                float v1 = h2f(hw[t], 1) + h2f(lw[t], 1);
                int ci = cq*8 + t*2;
                a += sw[ci*9 + tap] * v0;
                a += sw[(ci+1)*9 + tap] * v1;
            }
        }
    }
    out[nbase + (size_t)y*256 + x0 + tid] = a;
}

// ---------------- launch ----------------
extern "C" void kernel_launch(void* const* d_in, const int* in_sizes, int n_in,
                              void* d_out, int out_size)
{
    const float* x     = (const float*)d_in[0];
    const float* g     = (const float*)d_in[1];
    const float* fx_w1 = (const float*)d_in[2];
    const float* fx_b1 = (const float*)d_in[3];
    const float* fx_w2 = (const float*)d_in[4];
    const float* fx_b2 = (const float*)d_in[5];
    const float* fx_w3 = (const float*)d_in[6];
    const float* fx_b3 = (const float*)d_in[7];
    const float* fg_w1 = (const float*)d_in[8];
    const float* fg_b1 = (const float*)d_in[9];
    const float* fg_w2 = (const float*)d_in[10];
    const float* fg_b2 = (const float*)d_in[11];
    const float* fg_w3 = (const float*)d_in[12];
    const float* fg_b3 = (const float*)d_in[13];
    const float* c1_w  = (const float*)d_in[14];
    const float* c1_b  = (const float*)d_in[15];
    const float* c2_w  = (const float*)d_in[16];
    const float* c2_b  = (const float*)d_in[17];
    const float* c3_w  = (const float*)d_in[18];
    const float* c3_b  = (const float*)d_in[19];
    float* out = (float*)d_out;

    __half *h1h, *h1l, *h2h, *h2l;
    float *xy; uint32_t *wq;
    cudaGetSymbolAddress((void**)&h1h, g_h1h);
    cudaGetSymbolAddress((void**)&h1l, g_h1l);
    cudaGetSymbolAddress((void**)&h2h, g_h2h);
    cudaGetSymbolAddress((void**)&h2l, g_h2l);
    cudaGetSymbolAddress((void**)&xy, g_xy);
    cudaGetSymbolAddress((void**)&wq, g_wq);

    const int PIX_BLOCKS = Nn*HW/256;      // 65536
    const int C64_BLOCKS = Nn*128*4;       // 8192
    const int OUT_BLOCKS = Nn*256*4;       // 16384

    const int SM64 = 78336 + 64*4;
    const int SM88 = 78336 + 88*4;
    const int SMO  = 2*(3*66*144) + 576*4;

    cudaFuncSetAttribute((const void*)conv64m<8, 64, true, false>,
                         cudaFuncAttributeMaxDynamicSharedMemorySize, SM64);
    cudaFuncSetAttribute((const void*)conv64m<11, 81, false, true>,
                         cudaFuncAttributeMaxDynamicSharedMemorySize, SM88);
    cudaFuncSetAttribute((const void*)conv_out1,
                         cudaFuncAttributeMaxDynamicSharedMemorySize, SMO);

    const int PQ64 = (9*4*8*32 + 255)/256;   // 36
    const int PQ88 = (9*4*11*32 + 255)/256;  // 50

    // x head
    conv_in_small<1><<<PIX_BLOCKS, 256>>>(x, fx_w1, fx_b1, h1h, h1l);
    prepack_wq<8, 64><<<PQ64, 256>>>(fx_w2, wq);
    conv64m<8, 64, true, false><<<C64_BLOCKS, 128, SM64>>>(h1h, h1l, wq, fx_b2, h2h, h2l, nullptr, nullptr, 0);
    prepack_wq<11, 81><<<PQ88, 256>>>(fx_w3, wq);
    conv64m<11, 81, false, true><<<C64_BLOCKS, 128, SM88>>>(h2h, h2l, wq, fx_b3, nullptr, nullptr, x, xy, 0);

    // g head
    conv_in_small<1><<<PIX_BLOCKS, 256>>>(g, fg_w1, fg_b1, h1h, h1l);
    prepack_wq<8, 64><<<PQ64, 256>>>(fg_w2, wq);
    conv64m<8, 64, true, false><<<C64_BLOCKS, 128, SM64>>>(h1h, h1l, wq, fg_b2, h2h, h2l, nullptr, nullptr, 0);
    prepack_wq<11, 81><<<PQ88, 256>>>(fg_w3, wq);
    conv64m<11, 81, false, true><<<C64_BLOCKS, 128, SM88>>>(h2h, h2l, wq, fg_b3, nullptr, nullptr, g, xy, 1);

    // fusion head
    conv_in_small<2><<<PIX_BLOCKS, 256>>>(xy, c1_w, c1_b, h1h, h1l);
    prepack_wq<8, 64><<<PQ64, 256>>>(c2_w, wq);
    conv64m<8, 64, true, false><<<C64_BLOCKS, 128, SM64>>>(h1h, h1l, wq, c2_b, h2h, h2l, nullptr, nullptr, 0);
    conv_out1<<<OUT_BLOCKS, 64, SMO>>>(h2h, h2l, c3_w, c3_b, out);
}